// round 9
// baseline (speedup 1.0000x reference)
#include <cuda_runtime.h>

// TensorReduce_88536455839845 — NeRF over-compositing, R8.
// Persistent double-buffered pipeline at 3 CTAs/SM (24 warps/SM, regs<=85):
// continuous load issue (no CLC wave bubbles) + enough TLP, fixing R6's
// starvation (16 warps @ 119 regs) while keeping R7's tanh sigmoid.
//
// rgba:     [65536, 192, 4] f32  (d_in[0])
// distance: [65536, 192]    f32  (d_in[1])
// out:      [65536, 3]      f32

#define NR_RAYS    65536
#define NR_SAMPLES 192
#define NR_CHUNKS  6

#define EPS_DIST   1e-5f
#define EPS_ALPHA  1e-8f
#define FAR_DELTA  1e4f

// sigmoid(x) = 0.5*tanh(x/2) + 0.5 ; single MUFU.TANH on sm_103a
__device__ __forceinline__ float fast_sigmoid(float x) {
    return fmaf(0.5f, __tanhf(0.5f * x), 0.5f);
}

struct RayBuf {
    float4 v[NR_CHUNKS];
    float  d[NR_CHUNKS];
};

__device__ __forceinline__ void load_ray(
    const float4* __restrict__ rgba, const float* __restrict__ dist,
    int ray, int lane, RayBuf& b)
{
    const float4* rr = rgba + (size_t)ray * NR_SAMPLES;
    const float*  rd = dist + (size_t)ray * NR_SAMPLES;
    #pragma unroll
    for (int k = 0; k < NR_CHUNKS; ++k) {
        int s = (k << 5) + lane;
        b.v[k] = __ldcs(&rr[s]);
        b.d[k] = __ldcs(&rd[s]);
    }
}

__device__ __forceinline__ void compute_ray(
    const RayBuf& b, int ray, int lane, float* __restrict__ out)
{
    const unsigned FULL = 0xffffffffu;

    float alpha[NR_CHUNKS];
    float incl[NR_CHUNKS];
    #pragma unroll
    for (int k = 0; k < NR_CHUNKS; ++k) {
        // d[s+1]: neighbor lane; lane 31 takes next chunk's lane 0.
        float nxt = (k < NR_CHUNKS - 1) ? __shfl_sync(FULL, b.d[k + 1], 0) : b.d[k];
        float d1  = __shfl_down_sync(FULL, b.d[k], 1);
        if (lane == 31) d1 = nxt;

        bool  last  = (k == NR_CHUNKS - 1) && (lane == 31);
        float delta = last ? FAR_DELTA : fabsf(d1 - b.d[k]);

        float density = (b.d[k] < EPS_DIST) ? 0.0f : fmaxf(b.v[k].w, 0.0f);

        float a  = 1.0f - __expf(-delta * density);
        alpha[k] = a;
        incl[k]  = 1.0f - a + EPS_ALPHA;       // strictly > 0
    }

    // 6 independent inclusive product scans, interleaved for ILP.
    #pragma unroll
    for (int off = 1; off < 32; off <<= 1) {
        #pragma unroll
        for (int k = 0; k < NR_CHUNKS; ++k) {
            float t = __shfl_up_sync(FULL, incl[k], off);
            if (lane >= off) incl[k] *= t;
        }
    }

    // Fold carry chain directly into accumulation (keeps live set small).
    float carry = 1.0f;
    float r_acc = 0.0f, g_acc = 0.0f, b_acc = 0.0f;
    #pragma unroll
    for (int k = 0; k < NR_CHUNKS; ++k) {
        float e = __shfl_up_sync(FULL, incl[k], 1);
        float excl = (lane == 0) ? 1.0f : e;
        float tot  = __shfl_sync(FULL, incl[k], 31);

        float w = alpha[k] * carry * excl;
        r_acc = fmaf(w, fast_sigmoid(b.v[k].x), r_acc);
        g_acc = fmaf(w, fast_sigmoid(b.v[k].y), g_acc);
        b_acc = fmaf(w, fast_sigmoid(b.v[k].z), b_acc);
        carry *= tot;
    }

    #pragma unroll
    for (int off = 16; off > 0; off >>= 1) {
        r_acc += __shfl_down_sync(FULL, r_acc, off);
        g_acc += __shfl_down_sync(FULL, g_acc, off);
        b_acc += __shfl_down_sync(FULL, b_acc, off);
    }

    if (lane == 0) {
        float* o = out + (size_t)ray * 3;
        o[0] = r_acc;
        o[1] = g_acc;
        o[2] = b_acc;
    }
}

__global__ __launch_bounds__(256, 3) void composite_kernel(
    const float4* __restrict__ rgba,
    const float*  __restrict__ dist,
    float*        __restrict__ out)
{
    int gwarp  = (blockIdx.x * blockDim.x + threadIdx.x) >> 5;
    int lane   = threadIdx.x & 31;
    int stride = (gridDim.x * blockDim.x) >> 5;   // total warps

    int ray = gwarp;
    if (ray >= NR_RAYS) return;

    RayBuf A, B;
    load_ray(rgba, dist, ray, lane, A);

    // Rotated 2-buffer pipeline: prefetch next ray before computing current.
    // All branch conditions are warp-uniform.
    while (true) {
        int n1 = ray + stride;
        if (n1 < NR_RAYS) load_ray(rgba, dist, n1, lane, B);
        compute_ray(A, ray, lane, out);
        if (n1 >= NR_RAYS) break;

        int n2 = n1 + stride;
        if (n2 < NR_RAYS) load_ray(rgba, dist, n2, lane, A);
        compute_ray(B, n1, lane, out);
        if (n2 >= NR_RAYS) break;

        ray = n2;
    }
}

extern "C" void kernel_launch(void* const* d_in, const int* in_sizes, int n_in,
                              void* d_out, int out_size) {
    const float4* rgba = (const float4*)d_in[0];
    const float*  dist = (const float*)d_in[1];
    float* out = (float*)d_out;

    int dev = 0, sms = 148;
    cudaGetDevice(&dev);
    cudaDeviceGetAttribute(&sms, cudaDevAttrMultiProcessorCount, dev);

    dim3 block(256);
    dim3 grid(sms * 3);   // persistent: exactly 3 CTAs per SM (24 warps/SM)
    composite_kernel<<<grid, block>>>(rgba, dist, out);
}

// round 11
// speedup vs baseline: 1.3631x; 1.3631x over previous
#include <cuda_runtime.h>

// TensorReduce_88536455839845 — NeRF over-compositing, R11.
// Base = R7 (best: 39.2us kernel, DRAM 82%). Changes:
//  - d[s+1] via direct L1-hit load instead of shfl_down + cross-chunk shfl
//    (-12 SHFL, removes cross-chunk dependency; extra LDG joins the burst)
//  - (redux.sync.add.f32 is NOT supported on sm_103 — plain shfl tree kept)
//  => SHFL count per warp-ray ~76 -> ~57.
//
// rgba:     [65536, 192, 4] f32  (d_in[0])
// distance: [65536, 192]    f32  (d_in[1])
// out:      [65536, 3]      f32

#define NR_RAYS    65536
#define NR_SAMPLES 192
#define NR_CHUNKS  6

#define EPS_DIST   1e-5f
#define EPS_ALPHA  1e-8f
#define FAR_DELTA  1e4f

// sigmoid(x) = 0.5*tanh(x/2) + 0.5 ; single MUFU.TANH on sm_103a
__device__ __forceinline__ float fast_sigmoid(float x) {
    return fmaf(0.5f, __tanhf(0.5f * x), 0.5f);
}

__global__ __launch_bounds__(256, 4) void composite_kernel(
    const float4* __restrict__ rgba,     // [N, S] float4
    const float*  __restrict__ dist,     // [N, S]
    float*        __restrict__ out)      // [N, 3]
{
    const unsigned FULL = 0xffffffffu;
    int gwarp = (blockIdx.x * blockDim.x + threadIdx.x) >> 5;
    int lane  = threadIdx.x & 31;
    if (gwarp >= NR_RAYS) return;

    const float4* ray_rgba = rgba + (size_t)gwarp * NR_SAMPLES;
    const float*  ray_dist = dist + (size_t)gwarp * NR_SAMPLES;

    // ---- Phase 1: ALL global loads up front ----
    // rgba streamed (no reuse); dist default policy (s+1 is an L1 hit on the
    // same line the neighboring lane fetches).
    float4 v[NR_CHUNKS];
    float  d0[NR_CHUNKS];
    float  d1[NR_CHUNKS];
    #pragma unroll
    for (int k = 0; k < NR_CHUNKS; ++k) {
        int s = (k << 5) + lane;
        v[k]  = __ldcs(&ray_rgba[s]);
        d0[k] = ray_dist[s];
        d1[k] = ray_dist[(s + 1 < NR_SAMPLES) ? s + 1 : s];
    }

    // ---- Phase 2: alpha / (1-alpha+eps) per chunk ----
    float alpha[NR_CHUNKS];
    float incl[NR_CHUNKS];
    #pragma unroll
    for (int k = 0; k < NR_CHUNKS; ++k) {
        bool  last  = (k == NR_CHUNKS - 1) && (lane == 31);
        float delta = last ? FAR_DELTA : fabsf(d1[k] - d0[k]);

        float density = (d0[k] < EPS_DIST) ? 0.0f : fmaxf(v[k].w, 0.0f);

        float a  = 1.0f - __expf(-delta * density);
        alpha[k] = a;
        incl[k]  = 1.0f - a + EPS_ALPHA;        // strictly > 0
    }

    // ---- Phase 3: 6 independent inclusive product scans, interleaved ----
    #pragma unroll
    for (int off = 1; off < 32; off <<= 1) {
        #pragma unroll
        for (int k = 0; k < NR_CHUNKS; ++k) {
            float t = __shfl_up_sync(FULL, incl[k], off);
            if (lane >= off) incl[k] *= t;
        }
    }

    // ---- Phase 4: carry chain + weighted accumulate ----
    float carry = 1.0f;
    float r_acc = 0.0f, g_acc = 0.0f, b_acc = 0.0f;
    #pragma unroll
    for (int k = 0; k < NR_CHUNKS; ++k) {
        float e    = __shfl_up_sync(FULL, incl[k], 1);
        float excl = (lane == 0) ? 1.0f : e;
        float tot  = __shfl_sync(FULL, incl[k], 31);

        float w = alpha[k] * carry * excl;
        r_acc = fmaf(w, fast_sigmoid(v[k].x), r_acc);
        g_acc = fmaf(w, fast_sigmoid(v[k].y), g_acc);
        b_acc = fmaf(w, fast_sigmoid(v[k].z), b_acc);
        carry *= tot;
    }

    // ---- Warp tree-reduce the 3 accumulators ----
    #pragma unroll
    for (int off = 16; off > 0; off >>= 1) {
        r_acc += __shfl_down_sync(FULL, r_acc, off);
        g_acc += __shfl_down_sync(FULL, g_acc, off);
        b_acc += __shfl_down_sync(FULL, b_acc, off);
    }

    if (lane == 0) {
        float* o = out + (size_t)gwarp * 3;
        o[0] = r_acc;
        o[1] = g_acc;
        o[2] = b_acc;
    }
}

extern "C" void kernel_launch(void* const* d_in, const int* in_sizes, int n_in,
                              void* d_out, int out_size) {
    const float4* rgba = (const float4*)d_in[0];
    const float*  dist = (const float*)d_in[1];
    float* out = (float*)d_out;

    dim3 block(256);
    dim3 grid((NR_RAYS * 32) / 256);   // 1 warp per ray
    composite_kernel<<<grid, block>>>(rgba, dist, out);
}

// round 12
// speedup vs baseline: 1.3748x; 1.0086x over previous
#include <cuda_runtime.h>

// TensorReduce_88536455839845 — NeRF over-compositing, R12.
// = R11 (best: 37.6us wall, DRAM 82%) with 64-thread CTAs (32768 blocks):
// fine-grained CLC replacement desynchronizes warp load/compute phases so the
// SM always has warps in load phase (fixes the collective-compute DRAM idle),
// and reg-limited occupancy rises to ~40 warps/SM.
//
// rgba:     [65536, 192, 4] f32  (d_in[0])
// distance: [65536, 192]    f32  (d_in[1])
// out:      [65536, 3]      f32

#define NR_RAYS    65536
#define NR_SAMPLES 192
#define NR_CHUNKS  6

#define EPS_DIST   1e-5f
#define EPS_ALPHA  1e-8f
#define FAR_DELTA  1e4f

// sigmoid(x) = 0.5*tanh(x/2) + 0.5 ; single MUFU.TANH on sm_103a
__device__ __forceinline__ float fast_sigmoid(float x) {
    return fmaf(0.5f, __tanhf(0.5f * x), 0.5f);
}

__global__ __launch_bounds__(64, 20) void composite_kernel(
    const float4* __restrict__ rgba,     // [N, S] float4
    const float*  __restrict__ dist,     // [N, S]
    float*        __restrict__ out)      // [N, 3]
{
    const unsigned FULL = 0xffffffffu;
    int gwarp = (blockIdx.x * blockDim.x + threadIdx.x) >> 5;
    int lane  = threadIdx.x & 31;
    if (gwarp >= NR_RAYS) return;

    const float4* ray_rgba = rgba + (size_t)gwarp * NR_SAMPLES;
    const float*  ray_dist = dist + (size_t)gwarp * NR_SAMPLES;

    // ---- Phase 1: ALL global loads up front ----
    // rgba streamed (no reuse); dist default policy (s+1 is an L1 hit on the
    // same line the neighboring lane fetches).
    float4 v[NR_CHUNKS];
    float  d0[NR_CHUNKS];
    float  d1[NR_CHUNKS];
    #pragma unroll
    for (int k = 0; k < NR_CHUNKS; ++k) {
        int s = (k << 5) + lane;
        v[k]  = __ldcs(&ray_rgba[s]);
        d0[k] = ray_dist[s];
        d1[k] = ray_dist[(s + 1 < NR_SAMPLES) ? s + 1 : s];
    }

    // ---- Phase 2: alpha / (1-alpha+eps) per chunk ----
    float alpha[NR_CHUNKS];
    float incl[NR_CHUNKS];
    #pragma unroll
    for (int k = 0; k < NR_CHUNKS; ++k) {
        bool  last  = (k == NR_CHUNKS - 1) && (lane == 31);
        float delta = last ? FAR_DELTA : fabsf(d1[k] - d0[k]);

        float density = (d0[k] < EPS_DIST) ? 0.0f : fmaxf(v[k].w, 0.0f);

        float a  = 1.0f - __expf(-delta * density);
        alpha[k] = a;
        incl[k]  = 1.0f - a + EPS_ALPHA;        // strictly > 0
    }

    // ---- Phase 3: 6 independent inclusive product scans, interleaved ----
    #pragma unroll
    for (int off = 1; off < 32; off <<= 1) {
        #pragma unroll
        for (int k = 0; k < NR_CHUNKS; ++k) {
            float t = __shfl_up_sync(FULL, incl[k], off);
            if (lane >= off) incl[k] *= t;
        }
    }

    // ---- Phase 4: carry chain + weighted accumulate ----
    float carry = 1.0f;
    float r_acc = 0.0f, g_acc = 0.0f, b_acc = 0.0f;
    #pragma unroll
    for (int k = 0; k < NR_CHUNKS; ++k) {
        float e    = __shfl_up_sync(FULL, incl[k], 1);
        float excl = (lane == 0) ? 1.0f : e;
        float tot  = __shfl_sync(FULL, incl[k], 31);

        float w = alpha[k] * carry * excl;
        r_acc = fmaf(w, fast_sigmoid(v[k].x), r_acc);
        g_acc = fmaf(w, fast_sigmoid(v[k].y), g_acc);
        b_acc = fmaf(w, fast_sigmoid(v[k].z), b_acc);
        carry *= tot;
    }

    // ---- Warp tree-reduce the 3 accumulators ----
    #pragma unroll
    for (int off = 16; off > 0; off >>= 1) {
        r_acc += __shfl_down_sync(FULL, r_acc, off);
        g_acc += __shfl_down_sync(FULL, g_acc, off);
        b_acc += __shfl_down_sync(FULL, b_acc, off);
    }

    if (lane == 0) {
        float* o = out + (size_t)gwarp * 3;
        o[0] = r_acc;
        o[1] = g_acc;
        o[2] = b_acc;
    }
}

extern "C" void kernel_launch(void* const* d_in, const int* in_sizes, int n_in,
                              void* d_out, int out_size) {
    const float4* rgba = (const float4*)d_in[0];
    const float*  dist = (const float*)d_in[1];
    float* out = (float*)d_out;

    dim3 block(64);
    dim3 grid(NR_RAYS / 2);   // 2 warps (2 rays) per CTA -> 32768 CTAs
    composite_kernel<<<grid, block>>>(rgba, dist, out);
}

// round 13
// speedup vs baseline: 1.5428x; 1.1222x over previous
#include <cuda_runtime.h>

// TensorReduce_88536455839845 — NeRF over-compositing, R13.
// Pair-ownership layout: each lane owns 2 consecutive samples; 3 chunks of 64
// samples (vs 6 of 32). dist loads 12->3 (float2 gives d[s],d[s+1] in-register,
// no line-straddle), warp scans 6->3 (scan over pair products), LDG instrs
// 18->9, SHFL ~57->~42. Keeps tanh sigmoid + front-batched load burst.
//
// rgba:     [65536, 192, 4] f32  (d_in[0])
// distance: [65536, 192]    f32  (d_in[1])
// out:      [65536, 3]      f32

#define NR_RAYS    65536
#define NR_SAMPLES 192
#define NR_PCHUNKS 3          // chunks of 64 samples (2 per lane)

#define EPS_DIST   1e-5f
#define EPS_ALPHA  1e-8f
#define FAR_DELTA  1e4f

// sigmoid(x) = 0.5*tanh(x/2) + 0.5 ; single MUFU.TANH on sm_103a
__device__ __forceinline__ float fast_sigmoid(float x) {
    return fmaf(0.5f, __tanhf(0.5f * x), 0.5f);
}

__global__ __launch_bounds__(128, 8) void composite_kernel(
    const float4* __restrict__ rgba,     // [N, S] float4
    const float*  __restrict__ dist,     // [N, S]
    float*        __restrict__ out)      // [N, 3]
{
    const unsigned FULL = 0xffffffffu;
    int gwarp = (blockIdx.x * blockDim.x + threadIdx.x) >> 5;
    int lane  = threadIdx.x & 31;
    if (gwarp >= NR_RAYS) return;

    const float4* ray_rgba = rgba + (size_t)gwarp * NR_SAMPLES;
    const float2* ray_dist2 = (const float2*)(dist + (size_t)gwarp * NR_SAMPLES);

    // ---- Phase 1: ALL global loads up front ----
    // Lane owns samples s0 = 64k + 2*lane and s1 = s0 + 1.
    float4 v0[NR_PCHUNKS], v1[NR_PCHUNKS];
    float2 d01[NR_PCHUNKS];
    #pragma unroll
    for (int k = 0; k < NR_PCHUNKS; ++k) {
        int s0 = (k << 6) + (lane << 1);
        v0[k]  = __ldcs(&ray_rgba[s0]);
        v1[k]  = __ldcs(&ray_rgba[s0 + 1]);
        d01[k] = ray_dist2[(k << 5) + lane];     // (dist[s0], dist[s0+1])
    }

    // ---- Phase 2: deltas / alphas / pair products ----
    // dnext (dist[s0+2]) = next lane's d01.x; lane 31 takes next chunk's lane 0.
    float alpha0[NR_PCHUNKS], alpha1[NR_PCHUNKS];
    float oma0[NR_PCHUNKS];
    float P[NR_PCHUNKS];                         // pair product, then scanned
    #pragma unroll
    for (int k = 0; k < NR_PCHUNKS; ++k) {
        float nxt   = (k < NR_PCHUNKS - 1) ? __shfl_sync(FULL, d01[k + 1].x, 0)
                                           : d01[k].y;
        float dnext = __shfl_down_sync(FULL, d01[k].x, 1);
        if (lane == 31) dnext = nxt;

        float delta0 = fabsf(d01[k].y - d01[k].x);
        bool  lastS  = (k == NR_PCHUNKS - 1) && (lane == 31);   // sample 191
        float delta1 = lastS ? FAR_DELTA : fabsf(dnext - d01[k].y);

        float den0 = (d01[k].x < EPS_DIST) ? 0.0f : fmaxf(v0[k].w, 0.0f);
        float den1 = (d01[k].y < EPS_DIST) ? 0.0f : fmaxf(v1[k].w, 0.0f);

        float a0 = 1.0f - __expf(-delta0 * den0);
        float a1 = 1.0f - __expf(-delta1 * den1);
        alpha0[k] = a0;
        alpha1[k] = a1;
        float o0 = 1.0f - a0 + EPS_ALPHA;        // strictly > 0
        float o1 = 1.0f - a1 + EPS_ALPHA;
        oma0[k] = o0;
        P[k]    = o0 * o1;
    }

    // ---- Phase 3: 3 independent inclusive product scans (pair domain) ----
    #pragma unroll
    for (int off = 1; off < 32; off <<= 1) {
        #pragma unroll
        for (int k = 0; k < NR_PCHUNKS; ++k) {
            float t = __shfl_up_sync(FULL, P[k], off);
            if (lane >= off) P[k] *= t;
        }
    }

    // ---- Phase 4: carry chain + weighted accumulate ----
    float carry = 1.0f;
    float r_acc = 0.0f, g_acc = 0.0f, b_acc = 0.0f;
    #pragma unroll
    for (int k = 0; k < NR_PCHUNKS; ++k) {
        float e    = __shfl_up_sync(FULL, P[k], 1);
        float excl = (lane == 0) ? 1.0f : e;     // product of pairs before this lane
        float tot  = __shfl_sync(FULL, P[k], 31);

        float trans0 = carry * excl;
        float trans1 = trans0 * oma0[k];
        float w0 = alpha0[k] * trans0;
        float w1 = alpha1[k] * trans1;

        r_acc = fmaf(w0, fast_sigmoid(v0[k].x), r_acc);
        g_acc = fmaf(w0, fast_sigmoid(v0[k].y), g_acc);
        b_acc = fmaf(w0, fast_sigmoid(v0[k].z), b_acc);
        r_acc = fmaf(w1, fast_sigmoid(v1[k].x), r_acc);
        g_acc = fmaf(w1, fast_sigmoid(v1[k].y), g_acc);
        b_acc = fmaf(w1, fast_sigmoid(v1[k].z), b_acc);

        carry *= tot;
    }

    // ---- Warp tree-reduce the 3 accumulators ----
    #pragma unroll
    for (int off = 16; off > 0; off >>= 1) {
        r_acc += __shfl_down_sync(FULL, r_acc, off);
        g_acc += __shfl_down_sync(FULL, g_acc, off);
        b_acc += __shfl_down_sync(FULL, b_acc, off);
    }

    if (lane == 0) {
        float* o = out + (size_t)gwarp * 3;
        o[0] = r_acc;
        o[1] = g_acc;
        o[2] = b_acc;
    }
}

extern "C" void kernel_launch(void* const* d_in, const int* in_sizes, int n_in,
                              void* d_out, int out_size) {
    const float4* rgba = (const float4*)d_in[0];
    const float*  dist = (const float*)d_in[1];
    float* out = (float*)d_out;

    dim3 block(128);
    dim3 grid((NR_RAYS * 32) / 128);   // 1 warp per ray, 4 warps per CTA
    composite_kernel<<<grid, block>>>(rgba, dist, out);
}